// round 1
// baseline (speedup 1.0000x reference)
#include <cuda_runtime.h>
#include <cstdint>
#include <math.h>

// ---------------------------------------------------------------------------
// Problem dims
// ---------------------------------------------------------------------------
#define T_STEPS 8192
#define IN_DIM  109
#define H_DIM   1024
#define G_DIM   4096   // 4*H
#define NBLK    128    // persistent blocks for recurrence (<= 148 SMs -> co-resident)

// ---------------------------------------------------------------------------
// Scratch (static device allocations; no cudaMalloc allowed)
// ---------------------------------------------------------------------------
__device__ float g_xproj[(size_t)T_STEPS * G_DIM];   // 134 MB, reused for both layers
__device__ float g_h0[(size_t)T_STEPS * H_DIM];      // layer0 hidden states
__device__ float g_h1[(size_t)T_STEPS * H_DIM];      // layer1 hidden states
__device__ float g_hbuf[2][2 * H_DIM];               // [layer][parity*1024 + j] ping-pong h
__device__ int   g_flags[2 * NBLK];                  // [layer*128 + block] step counters

// ---------------------------------------------------------------------------
// Memory-order helpers
// ---------------------------------------------------------------------------
__device__ __forceinline__ int ld_acq(const int* p) {
    int v;
    asm volatile("ld.acquire.gpu.b32 %0, [%1];" : "=r"(v) : "l"(p) : "memory");
    return v;
}
__device__ __forceinline__ void st_rel(int* p, int v) {
    asm volatile("st.release.gpu.b32 [%0], %1;" :: "l"(p), "r"(v) : "memory");
}
__device__ __forceinline__ float4 ld_cv4(const float4* p) {
    float4 v;
    asm volatile("ld.global.cv.v4.f32 {%0,%1,%2,%3}, [%4];"
                 : "=f"(v.x), "=f"(v.y), "=f"(v.z), "=f"(v.w) : "l"(p) : "memory");
    return v;
}

__device__ __forceinline__ float sigmoidf_(float x) {
    return 1.0f / (1.0f + expf(-x));
}

// ---------------------------------------------------------------------------
// Init: zero flags + h ping-pong buffers (must run every launch; statics keep
// state from the previous launch)
// ---------------------------------------------------------------------------
__global__ void init_kernel() {
    int i = blockIdx.x * blockDim.x + threadIdx.x;
    if (i < 2 * NBLK) g_flags[i] = 0;
    if (i < 2 * 2 * H_DIM) ((float*)g_hbuf)[i] = 0.0f;
}

// ---------------------------------------------------------------------------
// GEMM:  C[m][n] = sum_k A[m][k]*B[n][k] + bias1[n] + bias2[n]
// A: [M][K] row-major, B: [N][K] row-major. M,N divisible by 128; K arbitrary.
// 128x128 block tile, 256 threads, 8x8 microtile, K-panels of 8.
// ---------------------------------------------------------------------------
__global__ __launch_bounds__(256) void gemm_nt_bias(
    const float* __restrict__ A, const float* __restrict__ B,
    const float* __restrict__ bias1, const float* __restrict__ bias2,
    float* __restrict__ C, int M, int N, int K)
{
    __shared__ float As[8][132];
    __shared__ float Bs[8][132];

    const int m0 = blockIdx.y * 128;
    const int n0 = blockIdx.x * 128;
    const int tid = threadIdx.x;
    const int lr  = tid >> 1;          // 0..127 : row within tile (for loads)
    const int lk4 = (tid & 1) * 4;     // 0 or 4 : k offset (for loads)
    const int ty  = tid >> 4;          // 0..15
    const int tx  = tid & 15;          // 0..15

    float acc[8][8];
#pragma unroll
    for (int i = 0; i < 8; i++)
#pragma unroll
        for (int j = 0; j < 8; j++) acc[i][j] = 0.0f;

    for (int k0 = 0; k0 < K; k0 += 8) {
#pragma unroll
        for (int e = 0; e < 4; e++) {
            int k = k0 + lk4 + e;
            float av = 0.0f, bv = 0.0f;
            if (k < K) {
                av = A[(size_t)(m0 + lr) * K + k];
                bv = B[(size_t)(n0 + lr) * K + k];
            }
            As[lk4 + e][lr] = av;
            Bs[lk4 + e][lr] = bv;
        }
        __syncthreads();
#pragma unroll
        for (int kk = 0; kk < 8; kk++) {
            float a[8], b[8];
            float4 a0 = *(const float4*)&As[kk][ty * 8];
            float4 a1 = *(const float4*)&As[kk][ty * 8 + 4];
            float4 b0 = *(const float4*)&Bs[kk][tx * 8];
            float4 b1 = *(const float4*)&Bs[kk][tx * 8 + 4];
            a[0]=a0.x; a[1]=a0.y; a[2]=a0.z; a[3]=a0.w;
            a[4]=a1.x; a[5]=a1.y; a[6]=a1.z; a[7]=a1.w;
            b[0]=b0.x; b[1]=b0.y; b[2]=b0.z; b[3]=b0.w;
            b[4]=b1.x; b[5]=b1.y; b[6]=b1.z; b[7]=b1.w;
#pragma unroll
            for (int i = 0; i < 8; i++)
#pragma unroll
                for (int j = 0; j < 8; j++)
                    acc[i][j] = fmaf(a[i], b[j], acc[i][j]);
        }
        __syncthreads();
    }

#pragma unroll
    for (int i = 0; i < 8; i++) {
        size_t row = (size_t)(m0 + ty * 8 + i) * N;
#pragma unroll
        for (int j = 0; j < 8; j++) {
            int n = n0 + tx * 8 + j;
            C[row + n] = acc[i][j] + bias1[n] + bias2[n];
        }
    }
}

// ---------------------------------------------------------------------------
// Persistent LSTM recurrence for one layer.
// 128 blocks x 256 threads. Block b owns h-indices [8b, 8b+8) i.e. 32 gate
// rows (4 gates x 8 j). Weights live in registers: thread (rg=tid/64,
// cg=tid%64) holds rows {rg*1024 + 8b + i, i<8}, cols {cg*4 + q*256 + e}.
// Chip-wide step barrier: per-block flag = #steps completed; warp 0 polls.
// ---------------------------------------------------------------------------
__global__ __launch_bounds__(256, 1) void lstm_layer_kernel(
    const float* __restrict__ Whh,   // [4096][1024]
    const float* __restrict__ xp,    // [8192][4096] precomputed input proj + biases
    float* __restrict__ h_all,       // [8192][1024]
    float* hbuf,                     // [2*1024] ping-pong
    int* flags)                      // [128]
{
    const int b   = blockIdx.x;
    const int tid = threadIdx.x;
    const int rg  = tid >> 6;        // gate 0..3 (i,f,g,o)
    const int cg  = tid & 63;        // 0..63
    const int lane = tid & 31;
    const int warp = tid >> 5;
    const int half = warp & 1;

    __shared__ float4 hs4[256];          // h[t-1] as 256 float4
    __shared__ float  red[4][2][8];      // [gate][warp-half][jloc]

    // Load weights into registers (one-time).
    float w[8][16];
#pragma unroll
    for (int i = 0; i < 8; i++) {
        const float* wr = Whh + (size_t)(rg * 1024 + b * 8 + i) * 1024 + cg * 4;
#pragma unroll
        for (int q = 0; q < 4; q++) {
            float4 t4 = *(const float4*)(wr + q * 256);
            w[i][q * 4 + 0] = t4.x; w[i][q * 4 + 1] = t4.y;
            w[i][q * 4 + 2] = t4.z; w[i][q * 4 + 3] = t4.w;
        }
    }

    float c_state = 0.0f;   // only meaningful for tid < 8

    for (int t = 0; t < T_STEPS; ++t) {
        // Prefetch x_proj for this block's 8 h-elements (combine threads).
        float xv0 = 0.f, xv1 = 0.f, xv2 = 0.f, xv3 = 0.f;
        if (tid < 8) {
            const float* xr = xp + (size_t)t * G_DIM + b * 8 + tid;
            xv0 = __ldcs(xr);
            xv1 = __ldcs(xr + 1024);
            xv2 = __ldcs(xr + 2048);
            xv3 = __ldcs(xr + 3072);
        }

        // Wait for all blocks to have completed step t-1.
        if (t > 0) {
            if (tid < 32) {
                for (;;) {
                    int m0 = ld_acq(&flags[tid]);
                    int m1 = ld_acq(&flags[tid + 32]);
                    int m2 = ld_acq(&flags[tid + 64]);
                    int m3 = ld_acq(&flags[tid + 96]);
                    int mn = min(min(m0, m1), min(m2, m3));
                    if (__all_sync(0xFFFFFFFFu, mn >= t)) break;
                }
            }
            __syncthreads();
        }

        // Stage h[t-1] (L1-bypassing loads; L1 is not coherent across SMs).
        {
            const float4* hsrc = (const float4*)(hbuf + ((t + 1) & 1) * H_DIM);
            hs4[tid] = ld_cv4(hsrc + tid);
        }
        __syncthreads();

        // Mat-vec partials: 8 rows x 16 cols per thread.
        float acc[8];
#pragma unroll
        for (int i = 0; i < 8; i++) acc[i] = 0.0f;
        float4 hq[4];
#pragma unroll
        for (int q = 0; q < 4; q++) hq[q] = hs4[cg + q * 64];
#pragma unroll
        for (int i = 0; i < 8; i++) {
#pragma unroll
            for (int q = 0; q < 4; q++) {
                acc[i] = fmaf(w[i][q * 4 + 0], hq[q].x, acc[i]);
                acc[i] = fmaf(w[i][q * 4 + 1], hq[q].y, acc[i]);
                acc[i] = fmaf(w[i][q * 4 + 2], hq[q].z, acc[i]);
                acc[i] = fmaf(w[i][q * 4 + 3], hq[q].w, acc[i]);
            }
        }
        // Reduce across the 32 lanes of each warp.
#pragma unroll
        for (int i = 0; i < 8; i++) {
#pragma unroll
            for (int off = 16; off > 0; off >>= 1)
                acc[i] += __shfl_xor_sync(0xFFFFFFFFu, acc[i], off);
        }
        if (lane == 0) {
#pragma unroll
            for (int i = 0; i < 8; i++) red[rg][half][i] = acc[i];
        }
        __syncthreads();

        // Combine gates + elementwise LSTM cell (threads 0..7, j = tid).
        if (tid < 8) {
            int j = tid;
            float si = red[0][0][j] + red[0][1][j] + xv0;
            float sf = red[1][0][j] + red[1][1][j] + xv1;
            float sg = red[2][0][j] + red[2][1][j] + xv2;
            float so = red[3][0][j] + red[3][1][j] + xv3;
            float ig = sigmoidf_(si);
            float fg = sigmoidf_(sf);
            float gg = tanhf(sg);
            float og = sigmoidf_(so);
            c_state = fg * c_state + ig * gg;
            float h  = og * tanhf(c_state);
            hbuf[(t & 1) * H_DIM + b * 8 + j] = h;
            h_all[(size_t)t * H_DIM + b * 8 + j] = h;
            __syncwarp(0x000000FFu);
            if (tid == 0) {
                __threadfence();
                st_rel(&flags[b], t + 1);
            }
        }
    }
}

// ---------------------------------------------------------------------------
// FC (109 outputs) + log_softmax. 8 timesteps per block, 256 threads.
// ---------------------------------------------------------------------------
__global__ __launch_bounds__(256) void fc_logsoftmax_kernel(
    const float* __restrict__ H,   // [8192][1024]
    const float* __restrict__ Wf,  // [109][1024]
    const float* __restrict__ bf,  // [109]
    float* __restrict__ out)       // [8192][109]
{
    __shared__ float ws[IN_DIM][68];
    __shared__ float hs[8][68];
    __shared__ float lg[8][112];

    const int t0  = blockIdx.x * 8;
    const int tid = threadIdx.x;
    const int tt  = tid & 7;       // timestep within tile
    const int n4  = tid >> 3;      // 0..31

    float acc[4] = {0.f, 0.f, 0.f, 0.f};

    for (int kc = 0; kc < H_DIM; kc += 64) {
        for (int idx = tid; idx < IN_DIM * 16; idx += 256) {
            int n = idx >> 4, k4 = idx & 15;
            *(float4*)&ws[n][k4 * 4] = *(const float4*)&Wf[(size_t)n * H_DIM + kc + k4 * 4];
        }
        for (int idx = tid; idx < 8 * 16; idx += 256) {
            int r = idx >> 4, k4 = idx & 15;
            *(float4*)&hs[r][k4 * 4] = *(const float4*)&H[(size_t)(t0 + r) * H_DIM + kc + k4 * 4];
        }
        __syncthreads();
#pragma unroll
        for (int k4 = 0; k4 < 16; k4++) {
            float4 hv = *(const float4*)&hs[tt][k4 * 4];
#pragma unroll
            for (int i = 0; i < 4; i++) {
                int n = n4 + i * 32;
                if (n < IN_DIM) {
                    float4 wv = *(const float4*)&ws[n][k4 * 4];
                    acc[i] += hv.x * wv.x + hv.y * wv.y + hv.z * wv.z + hv.w * wv.w;
                }
            }
        }
        __syncthreads();
    }

#pragma unroll
    for (int i = 0; i < 4; i++) {
        int n = n4 + i * 32;
        if (n < IN_DIM) lg[tt][n] = acc[i] + bf[n];
    }
    __syncthreads();

    // log_softmax: one warp per timestep.
    const int wp = tid >> 5, lane = tid & 31;
    {
        int t = wp;
        float v0 = (lane       < IN_DIM) ? lg[t][lane]       : -INFINITY;
        float v1 = (lane + 32  < IN_DIM) ? lg[t][lane + 32]  : -INFINITY;
        float v2 = (lane + 64  < IN_DIM) ? lg[t][lane + 64]  : -INFINITY;
        float v3 = (lane + 96  < IN_DIM) ? lg[t][lane + 96]  : -INFINITY;
        float mx = fmaxf(fmaxf(v0, v1), fmaxf(v2, v3));
#pragma unroll
        for (int o = 16; o > 0; o >>= 1) mx = fmaxf(mx, __shfl_xor_sync(0xFFFFFFFFu, mx, o));
        float se = expf(v0 - mx) + expf(v1 - mx) + expf(v2 - mx) + expf(v3 - mx);
#pragma unroll
        for (int o = 16; o > 0; o >>= 1) se += __shfl_xor_sync(0xFFFFFFFFu, se, o);
        float ls = mx + logf(se);
        size_t row = (size_t)(t0 + t) * IN_DIM;
        if (lane      < IN_DIM) out[row + lane]      = v0 - ls;
        if (lane + 32 < IN_DIM) out[row + lane + 32] = v1 - ls;
        if (lane + 64 < IN_DIM) out[row + lane + 64] = v2 - ls;
        if (lane + 96 < IN_DIM) out[row + lane + 96] = v3 - ls;
    }
}

// ---------------------------------------------------------------------------
// Launch
// ---------------------------------------------------------------------------
extern "C" void kernel_launch(void* const* d_in, const int* in_sizes, int n_in,
                              void* d_out, int out_size)
{
    const float* input  = (const float*)d_in[0];   // [8192,109]
    const float* W_ih0  = (const float*)d_in[1];   // [4096,109]
    const float* W_hh0  = (const float*)d_in[2];   // [4096,1024]
    const float* b_ih0  = (const float*)d_in[3];
    const float* b_hh0  = (const float*)d_in[4];
    const float* W_ih1  = (const float*)d_in[5];   // [4096,1024]
    const float* W_hh1  = (const float*)d_in[6];   // [4096,1024]
    const float* b_ih1  = (const float*)d_in[7];
    const float* b_hh1  = (const float*)d_in[8];
    const float* fc_w   = (const float*)d_in[9];   // [109,1024]
    const float* fc_b   = (const float*)d_in[10];
    float* out = (float*)d_out;

    static float* p_xproj = nullptr;
    static float* p_h0 = nullptr;
    static float* p_h1 = nullptr;
    static float* p_hbuf = nullptr;
    static int*   p_flags = nullptr;
    if (!p_xproj) {
        cudaGetSymbolAddress((void**)&p_xproj, g_xproj);
        cudaGetSymbolAddress((void**)&p_h0,    g_h0);
        cudaGetSymbolAddress((void**)&p_h1,    g_h1);
        cudaGetSymbolAddress((void**)&p_hbuf,  g_hbuf);
        cudaGetSymbolAddress((void**)&p_flags, g_flags);
    }

    // 1) reset barrier flags + h ping-pong buffers
    init_kernel<<<17, 256>>>();

    // 2) x_proj0 = input @ W_ih0^T + b_ih0 + b_hh0
    {
        dim3 grid(G_DIM / 128, T_STEPS / 128);
        gemm_nt_bias<<<grid, 256>>>(input, W_ih0, b_ih0, b_hh0,
                                    p_xproj, T_STEPS, G_DIM, IN_DIM);
    }

    // 3) layer-0 recurrence
    lstm_layer_kernel<<<NBLK, 256>>>(W_hh0, p_xproj, p_h0,
                                     p_hbuf + 0, p_flags + 0);

    // 4) x_proj1 = h0 @ W_ih1^T + b_ih1 + b_hh1
    {
        dim3 grid(G_DIM / 128, T_STEPS / 128);
        gemm_nt_bias<<<grid, 256>>>(p_h0, W_ih1, b_ih1, b_hh1,
                                    p_xproj, T_STEPS, G_DIM, H_DIM);
    }

    // 5) layer-1 recurrence
    lstm_layer_kernel<<<NBLK, 256>>>(W_hh1, p_xproj, p_h1,
                                     p_hbuf + 2 * H_DIM, p_flags + NBLK);

    // 6) FC + log_softmax
    fc_logsoftmax_kernel<<<T_STEPS / 8, 256>>>(p_h1, fc_w, fc_b, out);
}

// round 7
// speedup vs baseline: 1.0236x; 1.0236x over previous
#include <cuda_runtime.h>
#include <cstdint>
#include <math.h>

// ---------------------------------------------------------------------------
// Problem dims
// ---------------------------------------------------------------------------
#define T_STEPS 8192
#define IN_DIM  109
#define H_DIM   1024
#define G_DIM   4096   // 4*H
#define NBLK    128    // persistent blocks (<=148 SMs, 1 CTA/SM -> co-resident)

// ---------------------------------------------------------------------------
// Scratch (static device allocations; no cudaMalloc allowed)
// ---------------------------------------------------------------------------
__device__ float g_xproj[(size_t)T_STEPS * G_DIM];   // 134 MB, reused for both layers
__device__ float g_h0[(size_t)T_STEPS * H_DIM];      // layer0 hidden states
__device__ float g_h1[(size_t)T_STEPS * H_DIM];      // layer1 hidden states
__device__ float g_hbuf[2][2 * H_DIM];               // [layer][parity*1024 + j] ping-pong h
__device__ int   g_flags[2 * NBLK];                  // [layer*128 + block] step counters

// ---------------------------------------------------------------------------
// Memory-order helpers (R1-proven)
// ---------------------------------------------------------------------------
__device__ __forceinline__ int ld_acq(const int* p) {
    int v;
    asm volatile("ld.acquire.gpu.b32 %0, [%1];" : "=r"(v) : "l"(p) : "memory");
    return v;
}
__device__ __forceinline__ void st_rel(int* p, int v) {
    asm volatile("st.release.gpu.b32 [%0], %1;" :: "l"(p), "r"(v) : "memory");
}
__device__ __forceinline__ float4 ld_cv4(const float4* p) {
    float4 v;
    asm volatile("ld.global.cv.v4.f32 {%0,%1,%2,%3}, [%4];"
                 : "=f"(v.x), "=f"(v.y), "=f"(v.z), "=f"(v.w) : "l"(p) : "memory");
    return v;
}
__device__ __forceinline__ void st_cg(float* p, float v) {
    asm volatile("st.global.cg.f32 [%0], %1;" :: "l"(p), "f"(v) : "memory");
}
__device__ __forceinline__ float sigmoidf_(float x) {
    return 1.0f / (1.0f + expf(-x));   // PRECISE, exactly as R1
}

// ---------------------------------------------------------------------------
// Init: zero flags + hbuf (R1 version; must run every launch)
// ---------------------------------------------------------------------------
__global__ void init_kernel() {
    int i = blockIdx.x * blockDim.x + threadIdx.x;
    if (i < 2 * NBLK) g_flags[i] = 0;
    if (i < 2 * 2 * H_DIM) ((float*)g_hbuf)[i] = 0.0f;
}

// ---------------------------------------------------------------------------
// GEMM:  C[m][n] = sum_k A[m][k]*B[n][k] + bias1[n] + bias2[n]   (R1 verbatim)
// ---------------------------------------------------------------------------
__global__ __launch_bounds__(256) void gemm_nt_bias(
    const float* __restrict__ A, const float* __restrict__ B,
    const float* __restrict__ bias1, const float* __restrict__ bias2,
    float* __restrict__ C, int M, int N, int K)
{
    __shared__ float As[8][132];
    __shared__ float Bs[8][132];

    const int m0 = blockIdx.y * 128;
    const int n0 = blockIdx.x * 128;
    const int tid = threadIdx.x;
    const int lr  = tid >> 1;
    const int lk4 = (tid & 1) * 4;
    const int ty  = tid >> 4;
    const int tx  = tid & 15;

    float acc[8][8];
#pragma unroll
    for (int i = 0; i < 8; i++)
#pragma unroll
        for (int j = 0; j < 8; j++) acc[i][j] = 0.0f;

    for (int k0 = 0; k0 < K; k0 += 8) {
#pragma unroll
        for (int e = 0; e < 4; e++) {
            int k = k0 + lk4 + e;
            float av = 0.0f, bv = 0.0f;
            if (k < K) {
                av = A[(size_t)(m0 + lr) * K + k];
                bv = B[(size_t)(n0 + lr) * K + k];
            }
            As[lk4 + e][lr] = av;
            Bs[lk4 + e][lr] = bv;
        }
        __syncthreads();
#pragma unroll
        for (int kk = 0; kk < 8; kk++) {
            float a[8], b[8];
            float4 a0 = *(const float4*)&As[kk][ty * 8];
            float4 a1 = *(const float4*)&As[kk][ty * 8 + 4];
            float4 b0 = *(const float4*)&Bs[kk][tx * 8];
            float4 b1 = *(const float4*)&Bs[kk][tx * 8 + 4];
            a[0]=a0.x; a[1]=a0.y; a[2]=a0.z; a[3]=a0.w;
            a[4]=a1.x; a[5]=a1.y; a[6]=a1.z; a[7]=a1.w;
            b[0]=b0.x; b[1]=b0.y; b[2]=b0.z; b[3]=b0.w;
            b[4]=b1.x; b[5]=b1.y; b[6]=b1.z; b[7]=b1.w;
#pragma unroll
            for (int i = 0; i < 8; i++)
#pragma unroll
                for (int j = 0; j < 8; j++)
                    acc[i][j] = fmaf(a[i], b[j], acc[i][j]);
        }
        __syncthreads();
    }

#pragma unroll
    for (int i = 0; i < 8; i++) {
        size_t row = (size_t)(m0 + ty * 8 + i) * N;
#pragma unroll
        for (int j = 0; j < 8; j++) {
            int n = n0 + tx * 8 + j;
            C[row + n] = acc[i][j] + bias1[n] + bias2[n];
        }
    }
}

// ---------------------------------------------------------------------------
// Persistent LSTM recurrence — R1 protocol (flags + threadfence + hbuf) and
// R1 numerics, with two value-preserving speedups:
//   (a) per-thread single-flag poll (syncthreads aggregates), nanosleep backoff
//   (b) tail activations computed one-per-lane in warp 0 via smem, identical
//       formulas; combine by threads 0..7 exactly as R1.
// ---------------------------------------------------------------------------
__global__ __launch_bounds__(256, 1) void lstm_layer_kernel(
    const float* __restrict__ Whh,   // [4096][1024]
    const float* __restrict__ xp,    // [8192][4096] precomputed input proj + biases
    float* __restrict__ h_all,       // [8192][1024]
    float* hbuf,                     // [2*1024] ping-pong
    int* flags)                      // [128]
{
    const int b   = blockIdx.x;
    const int tid = threadIdx.x;
    const int rg  = tid >> 6;        // gate 0..3 (i,f,g,o)
    const int cg  = tid & 63;        // 0..63
    const int lane = tid & 31;
    const int warp = tid >> 5;
    const int half = warp & 1;

    __shared__ float4 hs4[256];          // h[t-1] as 256 float4
    __shared__ float  red[4][2][8];      // [gate][warp-half][jloc]
    __shared__ float  actbuf[32];        // [jj*4 + g] activations

    // Load weights into registers (one-time, R1 layout).
    float w[8][16];
#pragma unroll
    for (int i = 0; i < 8; i++) {
        const float* wr = Whh + (size_t)(rg * 1024 + b * 8 + i) * 1024 + cg * 4;
#pragma unroll
        for (int q = 0; q < 4; q++) {
            float4 t4 = *(const float4*)(wr + q * 256);
            w[i][q * 4 + 0] = t4.x; w[i][q * 4 + 1] = t4.y;
            w[i][q * 4 + 2] = t4.z; w[i][q * 4 + 3] = t4.w;
        }
    }

    float c_state = 0.0f;   // only meaningful for tid < 8

    for (int t = 0; t < T_STEPS; ++t) {
        // Prefetch x_proj: warp 0, one scalar per lane. Lane L=(4*jj+g) holds
        // gate g of element jj — same values R1 loaded as xv0..xv3.
        float xv = 0.0f;
        if (tid < 32)
            xv = __ldcs(xp + (size_t)t * G_DIM + (tid & 3) * H_DIM + b * 8 + (tid >> 2));

        // Wait for all blocks to have completed step t-1.
        // Per-thread poll: thread i (<128) spins on flags[i] only; the
        // __syncthreads aggregates (same release->acquire->barrier chain R1
        // already relied on for hbuf visibility). nanosleep backoff keeps L2
        // pressure off the producers' release stores.
        if (t > 0) {
            if (tid < NBLK) {
                while (ld_acq(&flags[tid]) < t) { __nanosleep(64); }
            }
            __syncthreads();
        }

        // Stage h[t-1] (L1-bypassing loads; L1 not coherent across SMs).
        {
            const float4* hsrc = (const float4*)(hbuf + ((t + 1) & 1) * H_DIM);
            hs4[tid] = ld_cv4(hsrc + tid);
        }
        __syncthreads();

        // Mat-vec partials: 8 rows x 16 cols per thread (R1 order).
        float acc[8];
#pragma unroll
        for (int i = 0; i < 8; i++) acc[i] = 0.0f;
        float4 hq[4];
#pragma unroll
        for (int q = 0; q < 4; q++) hq[q] = hs4[cg + q * 64];
#pragma unroll
        for (int i = 0; i < 8; i++) {
#pragma unroll
            for (int q = 0; q < 4; q++) {
                acc[i] = fmaf(w[i][q * 4 + 0], hq[q].x, acc[i]);
                acc[i] = fmaf(w[i][q * 4 + 1], hq[q].y, acc[i]);
                acc[i] = fmaf(w[i][q * 4 + 2], hq[q].z, acc[i]);
                acc[i] = fmaf(w[i][q * 4 + 3], hq[q].w, acc[i]);
            }
        }
        // Reduce across the 32 lanes of each warp (R1 order).
#pragma unroll
        for (int i = 0; i < 8; i++) {
#pragma unroll
            for (int off = 16; off > 0; off >>= 1)
                acc[i] += __shfl_xor_sync(0xFFFFFFFFu, acc[i], off);
        }
        if (lane == 0) {
#pragma unroll
            for (int i = 0; i < 8; i++) red[rg][half][i] = acc[i];
        }
        __syncthreads();

        // Tail phase 1: warp 0, one activation per lane. Identical inputs and
        // formulas to R1's serial tail: pre = (red[g][0][j]+red[g][1][j])+xv.
        if (tid < 32) {
            const int jj = tid >> 2;
            const int g  = tid & 3;
            float pre = red[g][0][jj] + red[g][1][jj] + xv;
            actbuf[tid] = (g == 2) ? tanhf(pre) : sigmoidf_(pre);
            __syncwarp(0xFFFFFFFFu);

            // Tail phase 2: threads 0..7 combine exactly as R1 (j = tid).
            if (tid < 8) {
                float ig = actbuf[tid * 4 + 0];
                float fg = actbuf[tid * 4 + 1];
                float gg = actbuf[tid * 4 + 2];
                float og = actbuf[tid * 4 + 3];
                c_state = fg * c_state + ig * gg;          // R1 expression
                float h  = og * tanhf(c_state);            // R1 expression
                hbuf[(t & 1) * H_DIM + b * 8 + tid] = h;
                __syncwarp(0x000000FFu);
                if (tid == 0) {
                    __threadfence();
                    st_rel(&flags[b], t + 1);
                }
                __syncwarp(0x000000FFu);
                // h_all store after the release: fence does not drain it
                // (its consumers are later kernels, ordered by stream).
                st_cg(h_all + (size_t)t * H_DIM + b * 8 + tid, h);
            }
        }
    }
}

// ---------------------------------------------------------------------------
// FC (109 outputs) + log_softmax. 8 timesteps per block, 256 threads.
// ---------------------------------------------------------------------------
__global__ __launch_bounds__(256) void fc_logsoftmax_kernel(
    const float* __restrict__ H,   // [8192][1024]
    const float* __restrict__ Wf,  // [109][1024]
    const float* __restrict__ bf,  // [109]
    float* __restrict__ out)       // [8192][109]
{
    __shared__ float ws[IN_DIM][68];
    __shared__ float hs[8][68];
    __shared__ float lg[8][112];

    const int t0  = blockIdx.x * 8;
    const int tid = threadIdx.x;
    const int tt  = tid & 7;
    const int n4  = tid >> 3;

    float acc[4] = {0.f, 0.f, 0.f, 0.f};

    for (int kc = 0; kc < H_DIM; kc += 64) {
        for (int idx = tid; idx < IN_DIM * 16; idx += 256) {
            int n = idx >> 4, k4 = idx & 15;
            *(float4*)&ws[n][k4 * 4] = *(const float4*)&Wf[(size_t)n * H_DIM + kc + k4 * 4];
        }
        for (int idx = tid; idx < 8 * 16; idx += 256) {
            int r = idx >> 4, k4 = idx & 15;
            *(float4*)&hs[r][k4 * 4] = *(const float4*)&H[(size_t)(t0 + r) * H_DIM + kc + k4 * 4];
        }
        __syncthreads();
#pragma unroll
        for (int k4 = 0; k4 < 16; k4++) {
            float4 hv = *(const float4*)&hs[tt][k4 * 4];
#pragma unroll
            for (int i = 0; i < 4; i++) {
                int n = n4 + i * 32;
                if (n < IN_DIM) {
                    float4 wv = *(const float4*)&ws[n][k4 * 4];
                    acc[i] += hv.x * wv.x + hv.y * wv.y + hv.z * wv.z + hv.w * wv.w;
                }
            }
        }
        __syncthreads();
    }

#pragma unroll
    for (int i = 0; i < 4; i++) {
        int n = n4 + i * 32;
        if (n < IN_DIM) lg[tt][n] = acc[i] + bf[n];
    }
    __syncthreads();

    const int wp = tid >> 5, lane = tid & 31;
    {
        int t = wp;
        float v0 = (lane       < IN_DIM) ? lg[t][lane]       : -INFINITY;
        float v1 = (lane + 32  < IN_DIM) ? lg[t][lane + 32]  : -INFINITY;
        float v2 = (lane + 64  < IN_DIM) ? lg[t][lane + 64]  : -INFINITY;
        float v3 = (lane + 96  < IN_DIM) ? lg[t][lane + 96]  : -INFINITY;
        float mx = fmaxf(fmaxf(v0, v1), fmaxf(v2, v3));
#pragma unroll
        for (int o = 16; o > 0; o >>= 1) mx = fmaxf(mx, __shfl_xor_sync(0xFFFFFFFFu, mx, o));
        float se = expf(v0 - mx) + expf(v1 - mx) + expf(v2 - mx) + expf(v3 - mx);
#pragma unroll
        for (int o = 16; o > 0; o >>= 1) se += __shfl_xor_sync(0xFFFFFFFFu, se, o);
        float ls = mx + logf(se);
        size_t row = (size_t)(t0 + t) * IN_DIM;
        if (lane      < IN_DIM) out[row + lane]      = v0 - ls;
        if (lane + 32 < IN_DIM) out[row + lane + 32] = v1 - ls;
        if (lane + 64 < IN_DIM) out[row + lane + 64] = v2 - ls;
        if (lane + 96 < IN_DIM) out[row + lane + 96] = v3 - ls;
    }
}

// ---------------------------------------------------------------------------
// Launch
// ---------------------------------------------------------------------------
extern "C" void kernel_launch(void* const* d_in, const int* in_sizes, int n_in,
                              void* d_out, int out_size)
{
    const float* input  = (const float*)d_in[0];   // [8192,109]
    const float* W_ih0  = (const float*)d_in[1];   // [4096,109]
    const float* W_hh0  = (const float*)d_in[2];   // [4096,1024]
    const float* b_ih0  = (const float*)d_in[3];
    const float* b_hh0  = (const float*)d_in[4];
    const float* W_ih1  = (const float*)d_in[5];   // [4096,1024]
    const float* W_hh1  = (const float*)d_in[6];   // [4096,1024]
    const float* b_ih1  = (const float*)d_in[7];
    const float* b_hh1  = (const float*)d_in[8];
    const float* fc_w   = (const float*)d_in[9];   // [109,1024]
    const float* fc_b   = (const float*)d_in[10];
    float* out = (float*)d_out;

    static float* p_xproj = nullptr;
    static float* p_h0 = nullptr;
    static float* p_h1 = nullptr;
    static float* p_hbuf = nullptr;
    static int*   p_flags = nullptr;
    if (!p_xproj) {
        cudaGetSymbolAddress((void**)&p_xproj, g_xproj);
        cudaGetSymbolAddress((void**)&p_h0,    g_h0);
        cudaGetSymbolAddress((void**)&p_h1,    g_h1);
        cudaGetSymbolAddress((void**)&p_hbuf,  g_hbuf);
        cudaGetSymbolAddress((void**)&p_flags, g_flags);
    }

    // 1) reset barrier flags + h ping-pong buffers
    init_kernel<<<17, 256>>>();

    // 2) x_proj0 = input @ W_ih0^T + b_ih0 + b_hh0
    {
        dim3 grid(G_DIM / 128, T_STEPS / 128);
        gemm_nt_bias<<<grid, 256>>>(input, W_ih0, b_ih0, b_hh0,
                                    p_xproj, T_STEPS, G_DIM, IN_DIM);
    }

    // 3) layer-0 recurrence
    lstm_layer_kernel<<<NBLK, 256>>>(W_hh0, p_xproj, p_h0,
                                     p_hbuf + 0, p_flags + 0);

    // 4) x_proj1 = h0 @ W_ih1^T + b_ih1 + b_hh1
    {
        dim3 grid(G_DIM / 128, T_STEPS / 128);
        gemm_nt_bias<<<grid, 256>>>(p_h0, W_ih1, b_ih1, b_hh1,
                                    p_xproj, T_STEPS, G_DIM, H_DIM);
    }

    // 5) layer-1 recurrence
    lstm_layer_kernel<<<NBLK, 256>>>(W_hh1, p_xproj, p_h1,
                                     p_hbuf + 2 * H_DIM, p_flags + NBLK);

    // 6) FC + log_softmax
    fc_logsoftmax_kernel<<<T_STEPS / 8, 256>>>(p_h1, fc_w, fc_b, out);
}